// round 1
// baseline (speedup 1.0000x reference)
#include <cuda_runtime.h>
#include <cstddef>

#define NNODES 50000
#define NEDGES 800000

// ---------------- static scratch (no allocations allowed) ----------------
__device__ float g_XNI[(size_t)NNODES * 128];
__device__ float g_XNJ[(size_t)NNODES * 128];
__device__ float g_H  [(size_t)NNODES * 128];
__device__ float g_EF [(size_t)NEDGES * 128];
__device__ float g_F1 [(size_t)NEDGES * 128];
__device__ float g_F2 [(size_t)NEDGES * 30];
__device__ float g_score[NEDGES];
__device__ float g_ex[NEDGES];
__device__ int   g_menc[NNODES];
__device__ float g_ssum[NNODES];
__device__ float g_X2[(size_t)NNODES * 128];
__device__ float g_X3[(size_t)NNODES * 30];

// ---------------- generic tiled SGEMM: C = A[MxK] @ B[KxN] (+bias) ----------------
#define BM 64
#define BN 64
#define BK 16

__global__ void sgemm_bias(const float* __restrict__ A, const float* __restrict__ B,
                           const float* __restrict__ bias, float* __restrict__ C,
                           int M, int N, int K) {
    __shared__ float As[BK][BM + 1];
    __shared__ float Bs[BK][BN + 1];
    const int tid = threadIdx.x;
    const int tm = (tid / 16) * 4;
    const int tn = (tid % 16) * 4;
    const int blockRow = blockIdx.y * BM;
    const int blockCol = blockIdx.x * BN;

    float acc[4][4] = {};

    for (int k0 = 0; k0 < K; k0 += BK) {
        // load A tile (BM x BK), 4 elems per thread
        #pragma unroll
        for (int i = tid; i < BM * BK; i += 256) {
            int m  = i / BK;
            int kk = i % BK;
            int gr = blockRow + m;
            int gk = k0 + kk;
            As[kk][m] = (gr < M && gk < K) ? A[(size_t)gr * K + gk] : 0.0f;
        }
        // load B tile (BK x BN)
        #pragma unroll
        for (int i = tid; i < BK * BN; i += 256) {
            int kk = i / BN;
            int n  = i % BN;
            int gk = k0 + kk;
            int gc = blockCol + n;
            Bs[kk][n] = (gk < K && gc < N) ? B[(size_t)gk * N + gc] : 0.0f;
        }
        __syncthreads();
        #pragma unroll
        for (int kk = 0; kk < BK; kk++) {
            float a[4], b[4];
            #pragma unroll
            for (int i = 0; i < 4; i++) a[i] = As[kk][tm + i];
            #pragma unroll
            for (int j = 0; j < 4; j++) b[j] = Bs[kk][tn + j];
            #pragma unroll
            for (int i = 0; i < 4; i++)
                #pragma unroll
                for (int j = 0; j < 4; j++)
                    acc[i][j] += a[i] * b[j];
        }
        __syncthreads();
    }

    #pragma unroll
    for (int i = 0; i < 4; i++) {
        int gr = blockRow + tm + i;
        if (gr >= M) continue;
        #pragma unroll
        for (int j = 0; j < 4; j++) {
            int gc = blockCol + tn + j;
            if (gc < N)
                C[(size_t)gr * N + gc] = acc[i][j] + (bias ? bias[gc] : 0.0f);
        }
    }
}

// ---------------- edge combine: f = leaky(EF + XNI[src] + XNJ[dst] + bias), score ----------------
__global__ void edge_combine(const float* __restrict__ EF, const float* __restrict__ XNI,
                             const float* __restrict__ XNJ, const int* __restrict__ src,
                             const int* __restrict__ dst, const float* __restrict__ bias,
                             const float* __restrict__ attn, float* __restrict__ F,
                             float* __restrict__ score, int E, int dout, int has_score) {
    int warp = (int)((blockIdx.x * (size_t)blockDim.x + threadIdx.x) >> 5);
    int lane = threadIdx.x & 31;
    if (warp >= E) return;
    int sn = src[warp];
    int dn = dst[warp];
    float acc = 0.0f;
    for (int c = lane; c < dout; c += 32) {
        float v = EF[(size_t)warp * dout + c]
                + XNI[(size_t)sn * dout + c]
                + XNJ[(size_t)dn * dout + c]
                + bias[c];
        v = v > 0.0f ? v : 0.01f * v;
        F[(size_t)warp * dout + c] = v;
        if (has_score) acc += v * attn[c];
    }
    if (has_score) {
        #pragma unroll
        for (int o = 16; o > 0; o >>= 1)
            acc += __shfl_down_sync(0xffffffffu, acc, o);
        if (lane == 0) score[warp] = acc;
    }
}

// ---------------- segment softmax over dst ----------------
__device__ __forceinline__ int enc_f(float f) {
    int i = __float_as_int(f);
    return i >= 0 ? i : (i ^ 0x7fffffff);
}
__device__ __forceinline__ float dec_f(int i) {
    return __int_as_float(i >= 0 ? i : (i ^ 0x7fffffff));
}

__global__ void seg_max(const float* __restrict__ score, const int* __restrict__ dst,
                        int* __restrict__ menc, int E) {
    int e = blockIdx.x * blockDim.x + threadIdx.x;
    if (e >= E) return;
    atomicMax(&menc[dst[e]], enc_f(score[e]));
}

__global__ void seg_expsum(const float* __restrict__ score, const int* __restrict__ dst,
                           const int* __restrict__ menc, float* __restrict__ ex,
                           float* __restrict__ ssum, int E) {
    int e = blockIdx.x * blockDim.x + threadIdx.x;
    if (e >= E) return;
    int d = dst[e];
    float m = dec_f(menc[d]);
    float ev = expf(score[e] - m);
    ex[e] = ev;
    atomicAdd(&ssum[d], ev);
}

// ---------------- weighted aggregation: hout[dst] += a * H[src] ----------------
__global__ void aggregate(const float* __restrict__ ex, const float* __restrict__ ssum,
                          const float* __restrict__ H, const int* __restrict__ src,
                          const int* __restrict__ dst, float* __restrict__ hout,
                          int E, int dout) {
    int warp = (int)((blockIdx.x * (size_t)blockDim.x + threadIdx.x) >> 5);
    int lane = threadIdx.x & 31;
    if (warp >= E) return;
    int sn = src[warp];
    int dn = dst[warp];
    float a = ex[warp] / ssum[dn];
    for (int c = lane; c < dout; c += 32) {
        atomicAdd(&hout[(size_t)dn * dout + c], a * H[(size_t)sn * dout + c]);
    }
}

// ---------------- host orchestration ----------------
static inline void sgemm_launch(const float* A, const float* B, const float* bias,
                                float* C, int M, int N, int K) {
    dim3 grid((N + BN - 1) / BN, (M + BM - 1) / BM);
    sgemm_bias<<<grid, 256>>>(A, B, bias, C, M, N, K);
}

extern "C" void kernel_launch(void* const* d_in, const int* in_sizes, int n_in,
                              void* d_out, int out_size) {
    const float* x    = (const float*)d_in[0];
    const float* e    = (const float*)d_in[1];
    const int*   src  = (const int*)d_in[2];
    const int*   dst  = (const int*)d_in[3];

    const float* W_n1  = (const float*)d_in[4];
    const float* b_n1  = (const float*)d_in[5];
    const float* W_ni1 = (const float*)d_in[6];
    const float* W_nj1 = (const float*)d_in[7];
    const float* W_f1  = (const float*)d_in[8];
    const float* attn1 = (const float*)d_in[9];
    const float* bias1 = (const float*)d_in[10];

    const float* W_n2  = (const float*)d_in[11];
    const float* b_n2  = (const float*)d_in[12];
    const float* W_ni2 = (const float*)d_in[13];
    const float* W_nj2 = (const float*)d_in[14];
    const float* W_f2  = (const float*)d_in[15];
    const float* attn2 = (const float*)d_in[16];
    const float* bias2 = (const float*)d_in[17];

    const float* W_n3  = (const float*)d_in[18];
    const float* b_n3  = (const float*)d_in[19];  (void)b_n3;
    const float* W_ni3 = (const float*)d_in[20];
    const float* W_nj3 = (const float*)d_in[21];
    const float* W_f3  = (const float*)d_in[22];
    const float* attn3 = (const float*)d_in[23];  (void)attn3;
    const float* bias3 = (const float*)d_in[24];

    float* out = (float*)d_out;

    float *XNI, *XNJ, *H, *EF, *F1, *F2, *score, *ex, *ssum, *X2, *X3;
    int* menc;
    cudaGetSymbolAddress((void**)&XNI,   g_XNI);
    cudaGetSymbolAddress((void**)&XNJ,   g_XNJ);
    cudaGetSymbolAddress((void**)&H,     g_H);
    cudaGetSymbolAddress((void**)&EF,    g_EF);
    cudaGetSymbolAddress((void**)&F1,    g_F1);
    cudaGetSymbolAddress((void**)&F2,    g_F2);
    cudaGetSymbolAddress((void**)&score, g_score);
    cudaGetSymbolAddress((void**)&ex,    g_ex);
    cudaGetSymbolAddress((void**)&ssum,  g_ssum);
    cudaGetSymbolAddress((void**)&X2,    g_X2);
    cudaGetSymbolAddress((void**)&X3,    g_X3);
    cudaGetSymbolAddress((void**)&menc,  g_menc);

    const int Nn = NNODES;
    const int Ee = NEDGES;
    const int edgeBlocks = (Ee + 7) / 8;          // 8 warps/block, warp per edge
    const int perThreadBlocks = (Ee + 255) / 256; // thread per edge

    // ================= Layer 1: di=128, do=128 =================
    sgemm_launch(x, W_ni1, nullptr, XNI, Nn, 128, 128);
    sgemm_launch(x, W_nj1, nullptr, XNJ, Nn, 128, 128);
    sgemm_launch(x, W_n1,  b_n1,   H,   Nn, 128, 128);
    sgemm_launch(e, W_f1,  nullptr, EF,  Ee, 128, 128);
    edge_combine<<<edgeBlocks, 256>>>(EF, XNI, XNJ, src, dst, bias1, attn1,
                                      F1, score, Ee, 128, 1);
    cudaMemsetAsync(menc, 0x80, (size_t)Nn * sizeof(int), 0);
    cudaMemsetAsync(ssum, 0,    (size_t)Nn * sizeof(float), 0);
    cudaMemsetAsync(X2,   0,    (size_t)Nn * 128 * sizeof(float), 0);
    seg_max<<<perThreadBlocks, 256>>>(score, dst, menc, Ee);
    seg_expsum<<<perThreadBlocks, 256>>>(score, dst, menc, ex, ssum, Ee);
    aggregate<<<edgeBlocks, 256>>>(ex, ssum, H, src, dst, X2, Ee, 128);

    // ================= Layer 2: di=128, do=30 =================
    sgemm_launch(X2, W_ni2, nullptr, XNI, Nn, 30, 128);
    sgemm_launch(X2, W_nj2, nullptr, XNJ, Nn, 30, 128);
    sgemm_launch(X2, W_n2,  b_n2,   H,   Nn, 30, 128);
    sgemm_launch(F1, W_f2,  nullptr, EF,  Ee, 30, 128);
    edge_combine<<<edgeBlocks, 256>>>(EF, XNI, XNJ, src, dst, bias2, attn2,
                                      F2, score, Ee, 30, 1);
    cudaMemsetAsync(menc, 0x80, (size_t)Nn * sizeof(int), 0);
    cudaMemsetAsync(ssum, 0,    (size_t)Nn * sizeof(float), 0);
    cudaMemsetAsync(X3,   0,    (size_t)Nn * 30 * sizeof(float), 0);
    seg_max<<<perThreadBlocks, 256>>>(score, dst, menc, Ee);
    seg_expsum<<<perThreadBlocks, 256>>>(score, dst, menc, ex, ssum, Ee);
    aggregate<<<edgeBlocks, 256>>>(ex, ssum, H, src, dst, X3, Ee, 30);

    // ================= Layer 3: di=30, do=64 (only f needed) =================
    sgemm_launch(X3, W_ni3, nullptr, XNI, Nn, 64, 30);
    sgemm_launch(X3, W_nj3, nullptr, XNJ, Nn, 64, 30);
    sgemm_launch(F2, W_f3,  nullptr, EF,  Ee, 64, 30);
    edge_combine<<<edgeBlocks, 256>>>(EF, XNI, XNJ, src, dst, bias3, nullptr,
                                      out, nullptr, Ee, 64, 0);

    (void)in_sizes; (void)n_in; (void)out_size;
}

// round 4
// speedup vs baseline: 2.2179x; 2.2179x over previous
#include <cuda_runtime.h>
#include <cstddef>

#define NN 50000
#define EE 800000

// ---------------- static scratch ----------------
__device__ float g_XNI[(size_t)NN * 128];
__device__ float g_XNJ[(size_t)NN * 128];
__device__ float g_H  [(size_t)NN * 128];
__device__ float g_F1 [(size_t)EE * 128];
__device__ float g_F2 [(size_t)EE * 32];
__device__ float g_X2 [(size_t)NN * 128];
__device__ float g_X3 [(size_t)NN * 32];
__device__ float g_score[EE];
__device__ float g_ex[EE];
__device__ int   g_menc[NN];
__device__ float g_ssum[NN];
// padded layer-2/3 weights (30 -> 32)
__device__ float g_Wni2[128 * 32], g_Wnj2[128 * 32], g_Wn2[128 * 32], g_Wf2[128 * 32];
__device__ float g_bn2[32], g_bias2[32], g_attn2[32];
__device__ float g_Wni3[32 * 64], g_Wnj3[32 * 64], g_Wf3[32 * 64];

// ---------------- zero-pad copy: in[R x C] -> out[newR x newC] ----------------
__global__ void pad2d(const float* __restrict__ in, float* __restrict__ out,
                      int R, int C, int newR, int newC) {
    int i = blockIdx.x * blockDim.x + threadIdx.x;
    if (i >= newR * newC) return;
    int r = i / newC, c = i % newC;
    out[i] = (r < R && c < C) ? in[r * C + c] : 0.0f;
}

// ---------------- fused GEMM ----------------
// MODE 0: C = A@B (+bias), with M guard (node GEMMs)
// MODE 1: edge fused: F = leaky(A@B + XNI[src] + XNJ[dst] + bias); score = sum(F*attn)
// MODE 2: edge fused, no score (layer 3)
// Requires N == BN (single column tile). For MODE>=1 M % 128 == 0.
template<int BN, int TM, int TN, int MODE>
__global__ __launch_bounds__(256) void gemm_k(
    const float* __restrict__ A, const float* __restrict__ B,
    float* __restrict__ C, const float* __restrict__ bias,
    const float* __restrict__ XNI, const float* __restrict__ XNJ,
    const int* __restrict__ src, const int* __restrict__ dst,
    const float* __restrict__ attn, float* __restrict__ score,
    int M, int K)
{
    constexpr int BM = 128, BK = 16;
    constexpr int TX = BN / TN;
    constexpr int TY = 256 / TX;
    static_assert(TY * TM == BM, "tiling mismatch");
    __shared__ float As[BK][BM];
    __shared__ float Bs[BK][BN];
    __shared__ float s_sc[BM];

    const int tid = threadIdx.x;
    const int tx = tid % TX, ty = tid / TX;
    const int row0 = blockIdx.x * BM;

    if (MODE == 1) { if (tid < BM) s_sc[tid] = 0.0f; }

    float acc[TM][TN];
    #pragma unroll
    for (int i = 0; i < TM; i++)
        #pragma unroll
        for (int j = 0; j < TN; j++) acc[i][j] = 0.0f;

    for (int k0 = 0; k0 < K; k0 += BK) {
        // A tile: BM x BK, float4 along K, stored transposed
        #pragma unroll
        for (int v = tid; v < BM * BK / 4; v += 256) {
            int r = v / (BK / 4), p = v % (BK / 4);
            int gr = row0 + r;
            float4 q = make_float4(0.f, 0.f, 0.f, 0.f);
            if (gr < M) q = *(const float4*)&A[(size_t)gr * K + k0 + p * 4];
            As[p * 4 + 0][r] = q.x;
            As[p * 4 + 1][r] = q.y;
            As[p * 4 + 2][r] = q.z;
            As[p * 4 + 3][r] = q.w;
        }
        // B tile: BK x BN (B row stride == BN)
        #pragma unroll
        for (int v = tid; v < BK * BN / 4; v += 256) {
            int r = v / (BN / 4), c = v % (BN / 4);
            *(float4*)&Bs[r][c * 4] = *(const float4*)&B[(size_t)(k0 + r) * BN + c * 4];
        }
        __syncthreads();
        #pragma unroll
        for (int k = 0; k < BK; k++) {
            float a[TM], b[TN];
            #pragma unroll
            for (int i = 0; i < TM; i += 4)
                *(float4*)&a[i] = *(const float4*)&As[k][ty * TM + i];
            #pragma unroll
            for (int j = 0; j < TN; j += 4)
                *(float4*)&b[j] = *(const float4*)&Bs[k][tx * TN + j];
            #pragma unroll
            for (int i = 0; i < TM; i++)
                #pragma unroll
                for (int j = 0; j < TN; j++)
                    acc[i][j] = fmaf(a[i], b[j], acc[i][j]);
        }
        __syncthreads();
    }

    const int col = tx * TN;
    float bv[TN];
    #pragma unroll
    for (int j = 0; j < TN; j += 4) {
        float4 q = bias ? *(const float4*)&bias[col + j] : make_float4(0.f, 0.f, 0.f, 0.f);
        *(float4*)&bv[j] = q;
    }

    if (MODE == 0) {
        #pragma unroll
        for (int i = 0; i < TM; i++) {
            int gr = row0 + ty * TM + i;
            if (gr < M) {
                #pragma unroll
                for (int j = 0; j < TN; j += 4) {
                    float4 o;
                    o.x = acc[i][j + 0] + bv[j + 0];
                    o.y = acc[i][j + 1] + bv[j + 1];
                    o.z = acc[i][j + 2] + bv[j + 2];
                    o.w = acc[i][j + 3] + bv[j + 3];
                    *(float4*)&C[(size_t)gr * BN + col + j] = o;
                }
            }
        }
    } else {
        float av[TN];
        if (MODE == 1) {
            #pragma unroll
            for (int j = 0; j < TN; j += 4)
                *(float4*)&av[j] = *(const float4*)&attn[col + j];
        }
        #pragma unroll
        for (int i = 0; i < TM; i++) {
            int gr = row0 + ty * TM + i;
            int sn = src[gr], dn = dst[gr];
            float srow = 0.0f;
            #pragma unroll
            for (int j = 0; j < TN; j += 4) {
                float4 xi = *(const float4*)&XNI[(size_t)sn * BN + col + j];
                float4 xj = *(const float4*)&XNJ[(size_t)dn * BN + col + j];
                float4 o;
                o.x = acc[i][j + 0] + xi.x + xj.x + bv[j + 0];
                o.y = acc[i][j + 1] + xi.y + xj.y + bv[j + 1];
                o.z = acc[i][j + 2] + xi.z + xj.z + bv[j + 2];
                o.w = acc[i][j + 3] + xi.w + xj.w + bv[j + 3];
                o.x = o.x > 0.f ? o.x : 0.01f * o.x;
                o.y = o.y > 0.f ? o.y : 0.01f * o.y;
                o.z = o.z > 0.f ? o.z : 0.01f * o.z;
                o.w = o.w > 0.f ? o.w : 0.01f * o.w;
                *(float4*)&C[(size_t)gr * BN + col + j] = o;
                if (MODE == 1)
                    srow += o.x * av[j] + o.y * av[j + 1] + o.z * av[j + 2] + o.w * av[j + 3];
            }
            if (MODE == 1) atomicAdd(&s_sc[ty * TM + i], srow);
        }
        if (MODE == 1) {
            __syncthreads();
            if (tid < BM) score[row0 + tid] = s_sc[tid];
        }
    }
}

// ---------------- segment softmax over dst ----------------
__device__ __forceinline__ int enc_f(float f) {
    int i = __float_as_int(f);
    return i >= 0 ? i : (i ^ 0x7fffffff);
}
__device__ __forceinline__ float dec_f(int i) {
    return __int_as_float(i >= 0 ? i : (i ^ 0x7fffffff));
}

__global__ void seg_max(const float* __restrict__ score, const int* __restrict__ dst,
                        int* __restrict__ menc, int E) {
    int e = blockIdx.x * blockDim.x + threadIdx.x;
    if (e >= E) return;
    atomicMax(&menc[dst[e]], enc_f(score[e]));
}

__global__ void seg_expsum(const float* __restrict__ score, const int* __restrict__ dst,
                           const int* __restrict__ menc, float* __restrict__ ex,
                           float* __restrict__ ssum, int E) {
    int e = blockIdx.x * blockDim.x + threadIdx.x;
    if (e >= E) return;
    int d = dst[e];
    float ev = expf(score[e] - dec_f(menc[d]));
    ex[e] = ev;
    atomicAdd(&ssum[d], ev);
}

// ---------------- weighted aggregation: out[dst] += a * H[src] (vector red) ----------------
template<int DO>
__global__ void aggregate_k(const float* __restrict__ ex, const float* __restrict__ ssum,
                            const float* __restrict__ H, const int* __restrict__ src,
                            const int* __restrict__ dst, float* __restrict__ out, int E) {
    constexpr int L = DO / 4;
    long long gt = (long long)blockIdx.x * blockDim.x + threadIdx.x;
    int e = (int)(gt / L), l = (int)(gt % L);
    if (e >= E) return;
    int dn = dst[e];
    float a = ex[e] / ssum[dn];
    float4 h = *(const float4*)&H[(size_t)src[e] * DO + l * 4];
    float* p = &out[(size_t)dn * DO + l * 4];
    asm volatile("red.global.add.v4.f32 [%0], {%1,%2,%3,%4};"
                 :: "l"(p), "f"(h.x * a), "f"(h.y * a), "f"(h.z * a), "f"(h.w * a)
                 : "memory");
}

// ---------------- host ----------------
extern "C" void kernel_launch(void* const* d_in, const int* in_sizes, int n_in,
                              void* d_out, int out_size) {
    const float* x    = (const float*)d_in[0];
    const float* e    = (const float*)d_in[1];
    const int*   src  = (const int*)d_in[2];
    const int*   dst  = (const int*)d_in[3];

    const float* W_n1  = (const float*)d_in[4];
    const float* b_n1  = (const float*)d_in[5];
    const float* W_ni1 = (const float*)d_in[6];
    const float* W_nj1 = (const float*)d_in[7];
    const float* W_f1  = (const float*)d_in[8];
    const float* attn1 = (const float*)d_in[9];
    const float* bias1 = (const float*)d_in[10];

    const float* W_n2  = (const float*)d_in[11];
    const float* b_n2  = (const float*)d_in[12];
    const float* W_ni2 = (const float*)d_in[13];
    const float* W_nj2 = (const float*)d_in[14];
    const float* W_f2  = (const float*)d_in[15];
    const float* attn2 = (const float*)d_in[16];
    const float* bias2 = (const float*)d_in[17];

    const float* W_ni3 = (const float*)d_in[20];
    const float* W_nj3 = (const float*)d_in[21];
    const float* W_f3  = (const float*)d_in[22];
    const float* bias3 = (const float*)d_in[24];

    float* out = (float*)d_out;

    float *XNI, *XNJ, *H, *F1, *F2, *X2, *X3, *score, *ex, *ssum;
    float *Wni2, *Wnj2, *Wn2, *Wf2, *bn2, *bias2p, *attn2p, *Wni3, *Wnj3, *Wf3;
    int* menc;
    cudaGetSymbolAddress((void**)&XNI, g_XNI);
    cudaGetSymbolAddress((void**)&XNJ, g_XNJ);
    cudaGetSymbolAddress((void**)&H,   g_H);
    cudaGetSymbolAddress((void**)&F1,  g_F1);
    cudaGetSymbolAddress((void**)&F2,  g_F2);
    cudaGetSymbolAddress((void**)&X2,  g_X2);
    cudaGetSymbolAddress((void**)&X3,  g_X3);
    cudaGetSymbolAddress((void**)&score, g_score);
    cudaGetSymbolAddress((void**)&ex,  g_ex);
    cudaGetSymbolAddress((void**)&ssum, g_ssum);
    cudaGetSymbolAddress((void**)&menc, g_menc);
    cudaGetSymbolAddress((void**)&Wni2, g_Wni2);
    cudaGetSymbolAddress((void**)&Wnj2, g_Wnj2);
    cudaGetSymbolAddress((void**)&Wn2,  g_Wn2);
    cudaGetSymbolAddress((void**)&Wf2,  g_Wf2);
    cudaGetSymbolAddress((void**)&bn2,  g_bn2);
    cudaGetSymbolAddress((void**)&bias2p, g_bias2);
    cudaGetSymbolAddress((void**)&attn2p, g_attn2);
    cudaGetSymbolAddress((void**)&Wni3, g_Wni3);
    cudaGetSymbolAddress((void**)&Wnj3, g_Wnj3);
    cudaGetSymbolAddress((void**)&Wf3,  g_Wf3);

    const int Nn = NN, Ee = EE;
    const int nodeGrid = (Nn + 127) / 128;
    const int edgeGrid = Ee / 128;
    const int perThread = (Ee + 255) / 256;

    // ---- pad layer-2/3 params (30 -> 32) ----
    pad2d<<<(128 * 32 + 255) / 256, 256>>>(W_ni2, Wni2, 128, 30, 128, 32);
    pad2d<<<(128 * 32 + 255) / 256, 256>>>(W_nj2, Wnj2, 128, 30, 128, 32);
    pad2d<<<(128 * 32 + 255) / 256, 256>>>(W_n2,  Wn2,  128, 30, 128, 32);
    pad2d<<<(128 * 32 + 255) / 256, 256>>>(W_f2,  Wf2,  128, 30, 128, 32);
    pad2d<<<1, 32>>>(b_n2,  bn2,    1, 30, 1, 32);
    pad2d<<<1, 32>>>(bias2, bias2p, 1, 30, 1, 32);
    pad2d<<<1, 32>>>(attn2, attn2p, 1, 30, 1, 32);
    pad2d<<<(32 * 64 + 255) / 256, 256>>>(W_ni3, Wni3, 30, 64, 32, 64);
    pad2d<<<(32 * 64 + 255) / 256, 256>>>(W_nj3, Wnj3, 30, 64, 32, 64);
    pad2d<<<(32 * 64 + 255) / 256, 256>>>(W_f3,  Wf3,  30, 64, 32, 64);

    // ================= Layer 1: di=128, do=128 =================
    gemm_k<128, 8, 8, 0><<<nodeGrid, 256>>>(x, W_ni1, XNI, nullptr,
        nullptr, nullptr, nullptr, nullptr, nullptr, nullptr, Nn, 128);
    gemm_k<128, 8, 8, 0><<<nodeGrid, 256>>>(x, W_nj1, XNJ, nullptr,
        nullptr, nullptr, nullptr, nullptr, nullptr, nullptr, Nn, 128);
    gemm_k<128, 8, 8, 0><<<nodeGrid, 256>>>(x, W_n1, H, b_n1,
        nullptr, nullptr, nullptr, nullptr, nullptr, nullptr, Nn, 128);
    gemm_k<128, 8, 8, 1><<<edgeGrid, 256>>>(e, W_f1, F1, bias1,
        XNI, XNJ, src, dst, attn1, score, Ee, 128);

    cudaMemsetAsync(menc, 0x80, (size_t)Nn * sizeof(int), 0);
    cudaMemsetAsync(ssum, 0,    (size_t)Nn * sizeof(float), 0);
    cudaMemsetAsync(X2,   0,    (size_t)Nn * 128 * sizeof(float), 0);
    seg_max<<<perThread, 256>>>(score, dst, menc, Ee);
    seg_expsum<<<perThread, 256>>>(score, dst, menc, ex, ssum, Ee);
    aggregate_k<128><<<((long long)Ee * 32 + 255) / 256, 256>>>(ex, ssum, H, src, dst, X2, Ee);

    // ================= Layer 2: di=128, do=30 (padded 32) =================
    gemm_k<32, 4, 4, 0><<<nodeGrid, 256>>>(X2, Wni2, XNI, nullptr,
        nullptr, nullptr, nullptr, nullptr, nullptr, nullptr, Nn, 128);
    gemm_k<32, 4, 4, 0><<<nodeGrid, 256>>>(X2, Wnj2, XNJ, nullptr,
        nullptr, nullptr, nullptr, nullptr, nullptr, nullptr, Nn, 128);
    gemm_k<32, 4, 4, 0><<<nodeGrid, 256>>>(X2, Wn2, H, bn2,
        nullptr, nullptr, nullptr, nullptr, nullptr, nullptr, Nn, 128);
    gemm_k<32, 4, 4, 1><<<edgeGrid, 256>>>(F1, Wf2, F2, bias2p,
        XNI, XNJ, src, dst, attn2p, score, Ee, 128);

    cudaMemsetAsync(menc, 0x80, (size_t)Nn * sizeof(int), 0);
    cudaMemsetAsync(ssum, 0,    (size_t)Nn * sizeof(float), 0);
    cudaMemsetAsync(X3,   0,    (size_t)Nn * 32 * sizeof(float), 0);
    seg_max<<<perThread, 256>>>(score, dst, menc, Ee);
    seg_expsum<<<perThread, 256>>>(score, dst, menc, ex, ssum, Ee);
    aggregate_k<32><<<((long long)Ee * 8 + 255) / 256, 256>>>(ex, ssum, H, src, dst, X3, Ee);

    // ================= Layer 3: di=30 (padded 32), do=64; only f =================
    gemm_k<64, 8, 4, 0><<<nodeGrid, 256>>>(X3, Wni3, XNI, nullptr,
        nullptr, nullptr, nullptr, nullptr, nullptr, nullptr, Nn, 32);
    gemm_k<64, 8, 4, 0><<<nodeGrid, 256>>>(X3, Wnj3, XNJ, nullptr,
        nullptr, nullptr, nullptr, nullptr, nullptr, nullptr, Nn, 32);
    gemm_k<64, 8, 4, 2><<<edgeGrid, 256>>>(F2, Wf3, out, bias3,
        XNI, XNJ, src, dst, nullptr, nullptr, Ee, 32);

    (void)in_sizes; (void)n_in; (void)out_size;
}